// round 12
// baseline (speedup 1.0000x reference)
#include <cuda_runtime.h>

typedef unsigned long long u64;

__device__ __forceinline__ u64 pk2(float x, float y) {
    u64 r; asm("mov.b64 %0,{%1,%2};" : "=l"(r) : "f"(x), "f"(y)); return r;
}
__device__ __forceinline__ void upk2(u64 v, float& x, float& y) {
    asm("mov.b64 {%0,%1},%2;" : "=f"(x), "=f"(y) : "l"(v));
}
__device__ __forceinline__ u64 ffma2(u64 a, u64 b, u64 c) {
    u64 d; asm("fma.rn.f32x2 %0,%1,%2,%3;" : "=l"(d) : "l"(a), "l"(b), "l"(c)); return d;
}

// packed butterfly over pair-index bit B (64 u64 regs)
template <int B>
__device__ __forceinline__ void vstage64(u64* v, float t) {
    u64 tp = pk2(t, t), tn = pk2(-t, -t);
#pragma unroll
    for (int a = 0; a < 64; ++a)
        if (!(a & (1 << B))) {
            u64 A = v[a], C = v[a | (1 << B)];
            v[a]            = ffma2(tn, C, A);
            v[a | (1 << B)] = ffma2(tp, A, C);
        }
}

// x-lo7 of M^{-1}(j) as a function of j-lo7 (E fold; bit 6 = j6, e6 term added via base)
__device__ __forceinline__ constexpr int XLO(int j) {
    return (j ^ (j >> 1) ^ ((j >> 2) & 0x55)) & 127;
}

__global__ void __launch_bounds__(32, 12)
qsim_kernel(const float* __restrict__ feats,
            const float* __restrict__ qp,
            float* __restrict__ out)
{
    // Aliased layouts over one buffer (4224 floats):
    //   T (start of layer, raw state x): addr = 33*(x&127) + (x>>7)      [pitch 33]
    //   D (mid-layer, j):  addr = 132*(j&31) + (j>>7) + 32*j5 + 64*j6    [pitch 132]
    __shared__ __align__(16) float buf[4224];
    __shared__ float tt[240];

    const int l = threadIdx.x;   // one warp per CTA
    const int b = blockIdx.x;

    // tan table + global cos product (folded into output scale G^2)
    float gpart = 1.0f;
    for (int i = l; i < 240; i += 32) {
        float s, c; sincosf(0.5f * qp[12 + i], &s, &c);
        tt[i] = s / c; gpart *= c;
    }
#pragma unroll
    for (int o = 16; o; o >>= 1) gpart *= __shfl_xor_sync(~0u, gpart, o);

    // embedding: raw state into T layout (unnormalized; 1/||s||^2 in output scale)
    const float2* f2 = reinterpret_cast<const float2*>(feats + (size_t)b * 2048);
    const float PIO2 = 1.5707963267948966f;
    float acc = 16.0f;   // padding ssq share: 64 * 0.25
#pragma unroll
    for (int v = 0; v < 32; ++v) {
        int p = v * 32 + l;
        float2 x = f2[p];
        float y0 = tanhf(x.x) * PIO2;
        float y1 = tanhf(x.y) * PIO2;
        acc += y0 * y0 + y1 * y1;
        int s0 = 2 * p;
        buf[33 * (s0 & 127) + (s0 >> 7)]             = y0;
        buf[33 * ((s0 + 1) & 127) + ((s0 + 1) >> 7)] = y1;
    }
#pragma unroll
    for (int v = 32; v < 64; ++v) {
        int s0 = 2 * (v * 32 + l);
        buf[33 * (s0 & 127) + (s0 >> 7)]             = 0.5f;
        buf[33 * ((s0 + 1) & 127) + ((s0 + 1) >> 7)] = 0.5f;
    }
#pragma unroll
    for (int o = 16; o; o >>= 1) acc += __shfl_xor_sync(~0u, acc, o);
    const float oscale = (gpart * gpart) / acc;

    // per-lane constants
    // pass-1: lane l holds x-hi5 = l; corresponding j-hi5 = P1(l) (A^{-1})
    int l0 = l & 1, l1 = (l >> 1) & 1, l2 = (l >> 2) & 1, l3 = (l >> 3) & 1, l4 = (l >> 4) & 1;
    int P1 = (l0 ^ l1 ^ l2) | ((l1 ^ l2) << 1) | ((l2 ^ l3 ^ l4) << 2)
           | ((l3 ^ l4) << 3) | (l4 << 4);
    int e6 = l0;   // j7 ^ j8 (feeds x6)
    const float* pLT0 = buf + l + (e6 ? 64 * 33 : 0);   // pass-1 load base, a5=0
    const float* pLT1 = buf + l + (e6 ? 0 : 64 * 33);   // pass-1 load base, a5=1
    float* pS1 = buf + P1;          // T12 store base (lane part = P1)
    const float* pD = buf + 132 * l;   // pass-2 load base (row = j-lo5 = l)
    float* pS2 = buf + 33 * l;      // end store base (lane part = 33*l)
    __syncwarp();

    u64 v[64];

#pragma unroll 1
    for (int L = 0; L < 20; ++L) {
        const float* tc = tt + L * 12;

        // ===== pass 1: E-folded load (T layout) + RY q11..q5 (j bits 0..6) =====
        {
            float t11 = tc[11];
#pragma unroll
            for (int a = 0; a < 64; ++a) {
                const float* base = (a & 32) ? pLT1 : pLT0;   // a5 selects bit-6 base
                const int r0 = XLO((a << 1)) & 63;            // c = 0
                const int r1 = XLO((a << 1) | 1) & 63;        // c = 1
                float x0 = base[33 * r0];
                float x1 = base[33 * r1];
                v[a] = pk2(fmaf(-t11, x1, x0), fmaf(t11, x0, x1));   // fold q11 (j0)
            }
        }
        vstage64<0>(v, tc[10]);   // j1
        vstage64<1>(v, tc[9]);
        vstage64<2>(v, tc[8]);
        vstage64<3>(v, tc[7]);
        vstage64<4>(v, tc[6]);
        vstage64<5>(v, tc[5]);    // j6
        __syncwarp();

        // ===== T12 store into D layout: imm = 132*(c+2*(a&15)) + 32*a4 + 64*a5 =====
#pragma unroll
        for (int a = 0; a < 64; ++a) {
            float x, y; upk2(v[a], x, y);
            const int imm = 132 * (2 * (a & 15)) + 32 * ((a >> 4) & 1) + 64 * ((a >> 5) & 1);
            pS1[imm]       = x;   // c = 0
            pS1[imm + 132] = y;   // c = 1
        }
        __syncwarp();

        // ===== pass 2: D load (row l) + RY q4..q0 (j bits 7..11) =====
        {
            float t4 = tc[4];
            u64 tn4 = pk2(-t4, -t4), tp4 = pk2(t4, t4);
#pragma unroll
            for (int k = 0; k < 8; ++k) {
#pragma unroll
                for (int a0 = 0; a0 < 2; ++a0) {
                    float4 f0 = *reinterpret_cast<const float4*>(pD + 4 * k + 64 * a0);
                    float4 f1 = *reinterpret_cast<const float4*>(pD + 4 * k + 32 + 64 * a0);
                    u64 p0 = pk2(f0.x, f1.x);   // (a1,a2)=(0,0), components c=j5
                    u64 p1 = pk2(f0.y, f1.y);   // (1,0)
                    u64 p2 = pk2(f0.z, f1.z);   // (0,1)
                    u64 p3 = pk2(f0.w, f1.w);   // (1,1)
                    const int base = a0 + 8 * k;
                    v[base]     = ffma2(tn4, p1, p0);   // fold q4 (j7 = a1)
                    v[base + 2] = ffma2(tp4, p0, p1);
                    v[base + 4] = ffma2(tn4, p3, p2);
                    v[base + 6] = ffma2(tp4, p2, p3);
                }
            }
        }
        vstage64<2>(v, tc[3]);   // j8
        vstage64<3>(v, tc[2]);
        vstage64<4>(v, tc[1]);
        vstage64<5>(v, tc[0]);   // j11

        if (L < 19) {
            __syncwarp();
            // ===== end store into T layout (raw state j): imm = 33*(32c+64a0) + (a>>1) =====
#pragma unroll
            for (int a = 0; a < 64; ++a) {
                float x, y; upk2(v[a], x, y);
                const int imm = 33 * 64 * (a & 1) + (a >> 1);
                pS2[imm]           = x;   // c = 0
                pS2[imm + 33 * 32] = y;   // c = 1
            }
            __syncwarp();
        } else {
            // ===== expvals from registers =====
            // c = j5 (q6); a0 = j6 (q5); a1..a5 = j7..j11 (q4..q0); l = j0..j4 (q11..q7)
            float S = 0.f, Tc = 0.f, T0 = 0.f, T1 = 0.f, T2 = 0.f, T3 = 0.f, T4 = 0.f, T5 = 0.f;
#pragma unroll
            for (int a = 0; a < 64; ++a) {
                float x, y; upk2(v[a], x, y);
                float px = x * x, py = y * y, ps = px + py;
                S += ps; Tc += py;
                if (a & 1)  T0 += ps;
                if (a & 2)  T1 += ps;
                if (a & 4)  T2 += ps;
                if (a & 8)  T3 += ps;
                if (a & 16) T4 += ps;
                if (a & 32) T5 += ps;
            }
            float val[12];
            val[0] = S - 2.f * T5;   // q0 = j11 = a5
            val[1] = S - 2.f * T4;
            val[2] = S - 2.f * T3;
            val[3] = S - 2.f * T2;
            val[4] = S - 2.f * T1;   // q4 = j7 = a1
            val[5] = S - 2.f * T0;   // q5 = j6 = a0
            val[6] = S - 2.f * Tc;   // q6 = j5 = component
#pragma unroll
            for (int q = 7; q < 12; ++q)
                val[q] = ((l >> (11 - q)) & 1) ? -S : S;   // q7..q11 = j4..j0 (lane bits)
#pragma unroll
            for (int q = 0; q < 12; ++q) {
#pragma unroll
                for (int o = 16; o; o >>= 1)
                    val[q] += __shfl_xor_sync(~0u, val[q], o);
            }
            if (l == 0) {
#pragma unroll
                for (int q = 0; q < 12; ++q)
                    out[(size_t)b * 12 + q] = val[q] * oscale;
            }
        }
    }
}

extern "C" void kernel_launch(void* const* d_in, const int* in_sizes, int n_in,
                              void* d_out, int out_size) {
    const float* feats = (const float*)d_in[0];
    const float* qp    = (const float*)d_in[1];
    float* out         = (float*)d_out;
    qsim_kernel<<<4096, 32>>>(feats, qp, out);
}

// round 13
// speedup vs baseline: 1.0382x; 1.0382x over previous
#include <cuda_runtime.h>

#define NT 64
typedef unsigned long long u64;

__device__ __forceinline__ u64 pk2(float x, float y) {
    u64 r; asm("mov.b64 %0,{%1,%2};" : "=l"(r) : "f"(x), "f"(y)); return r;
}
__device__ __forceinline__ void upk2(u64 v, float& x, float& y) {
    asm("mov.b64 {%0,%1},%2;" : "=f"(x), "=f"(y) : "l"(v));
}
__device__ __forceinline__ u64 ffma2(u64 a, u64 b, u64 c) {
    u64 d; asm("fma.rn.f32x2 %0,%1,%2,%3;" : "=l"(d) : "l"(a), "l"(b), "l"(c)); return d;
}

// packed butterfly over pair-index bit B
template <int B>
__device__ __forceinline__ void vstage(u64* v, float t) {
    u64 tp = pk2(t, t), tn = pk2(-t, -t);
#pragma unroll
    for (int a = 0; a < 32; ++a)
        if (!(a & (1 << B))) {
            u64 A = v[a], Bv = v[a | (1 << B)];
            v[a]            = ffma2(tn, Bv, A);
            v[a | (1 << B)] = ffma2(tp, A, Bv);
        }
}

// register-pair index for pass-1 load row-pair q: a = (f0^{-1}(2q)) >> 1
__device__ __forceinline__ constexpr int AQ(int q) {
    int q0 = q & 1, q1 = (q >> 1) & 1, q2 = (q >> 2) & 1, q3 = (q >> 3) & 1, q4 = (q >> 4) & 1;
    return (q0 ^ q1 ^ q2) | ((q1 ^ q2) << 1) | ((q2 ^ q3 ^ q4) << 2)
         | ((q3 ^ q4) << 3) | (q4 << 4);
}

#define PITCH 68
// tan table lives in the pad columns (64..67) of buf rows 0..59 — columns that no
// state access ever touches (all state traffic has column in [0,63]).
#define TTIDX(i) (((i) >> 2) * PITCH + 64 + ((i) & 3))

__global__ void __launch_bounds__(NT, 12)
qsim_kernel(const float* __restrict__ feats,
            const float* __restrict__ qp,
            float* __restrict__ out)
{
    // layout T: element (i_lo, i_hi) at i_lo*PITCH + i_hi  (pad 68 -> bank rot by 4/row)
    __shared__ float buf[64 * PITCH];
    __shared__ float wred[2], gred[2];
    __shared__ float oscale_s;
    __shared__ float rsum[2][12];

    const int u    = threadIdx.x;   // 0..63
    const int lane = u & 31;
    const int b    = blockIdx.x;

    // tan table (into pad) + global cos product (cos factors -> output scale G^2)
    float gpart = 1.0f;
    for (int i = u; i < 240; i += NT) {
        float s, c; sincosf(0.5f * qp[12 + i], &s, &c);
        buf[TTIDX(i)] = s / c; gpart *= c;
    }
#pragma unroll
    for (int o = 16; o; o >>= 1) gpart *= __shfl_xor_sync(~0u, gpart, o);
    if (lane == 0) gred[u >> 5] = gpart;

    // embedding: raw state into T layout (elem s at (s&63)*PITCH + (s>>6))
    const float2* f2 = reinterpret_cast<const float2*>(feats + (size_t)b * 2048);
    const float PIO2 = 1.5707963267948966f;
    float acc = 8.0f;
#pragma unroll
    for (int v = 0; v < 16; ++v) {
        int p = v * 64 + u;
        float2 x = f2[p];
        float y0 = tanhf(x.x) * PIO2;
        float y1 = tanhf(x.y) * PIO2;
        acc += y0 * y0 + y1 * y1;
        int s = 2 * p;
        buf[(s & 63) * PITCH + (s >> 6)]       = y0;
        buf[((s + 1) & 63) * PITCH + (s >> 6)] = y1;
    }
#pragma unroll
    for (int v = 16; v < 32; ++v) {
        int s = 2 * (v * 64 + u);
        buf[(s & 63) * PITCH + (s >> 6)]       = 0.5f;
        buf[((s + 1) & 63) * PITCH + (s >> 6)] = 0.5f;
    }
#pragma unroll
    for (int o = 16; o; o >>= 1) acc += __shfl_xor_sync(~0u, acc, o);
    if (lane == 0) wred[u >> 5] = acc;
    __syncthreads();
    if (u == 0) {
        float G = gred[0] * gred[1];
        oscale_s = (G * G) / (wred[0] + wred[1]);
    }

    // per-thread constants
    // i_hi = H(u) = Mhi^{-1}(u)
    int u0 = u & 1, u1 = (u >> 1) & 1, u2b = (u >> 2) & 1;
    int u3 = (u >> 3) & 1, u4 = (u >> 4) & 1, u5 = (u >> 5) & 1;
    int Hh = (u0 ^ u1) | ((u1 ^ u2b ^ u3) << 1) | ((u2b ^ u3) << 2)
           | ((u3 ^ u4 ^ u5) << 3) | ((u4 ^ u5) << 4) | (u5 << 5);
    int e = u0 ^ u1;                         // i6 of this thread's dst block
    const float* pL = buf + u;               // pass-1 load base (col u, + m*PITCH imm)
    float* B0 = buf + Hh + (e ? 32 * PITCH : 0);   // pass-1 store, rows 0..31
    float* B1 = buf + Hh + (e ? 0 : 32 * PITCH);   // pass-1 store, rows 32..63
    float* pld = buf + u * PITCH;            // pass-2 base (in-place)
    float esgn = e ? -1.0f : 1.0f;

#pragma unroll 1
    for (int L = 0; L < 20; ++L) {
        const int tb = L * 12;
        // per-layer tan coefficients (warp-uniform broadcast loads from pad)
        float tcv[12];
#pragma unroll
        for (int k = 0; k < 12; ++k) tcv[k] = buf[TTIDX(tb + k)];

        // ===== pass 1: entangling gather (addressing-free) + RY qubits 11..6 =====
        u64 vr[32];
        {
            float t11 = tcv[11];
            u64 tm = pk2(-t11, t11);
#pragma unroll
            for (int q = 0; q < 32; ++q) {
                float A = pL[(2 * q) * PITCH];
                float Bv = pL[(2 * q + 1) * PITCH];
                u64 ab = pk2(A, Bv), ba = pk2(Bv, A);
                // role: even row holds comp0 iff (q&1)==0
                vr[AQ(q)] = (q & 1) ? ffma2(tm, ab, ba) : ffma2(tm, ba, ab);
            }
        }
        vstage<0>(vr, tcv[10]);
        vstage<1>(vr, tcv[9]);
        vstage<2>(vr, tcv[8]);
        vstage<3>(vr, tcv[7]);
        vstage<4>(vr, esgn * tcv[6]);   // e-swapped pairing on bit5 => R(-t)
        __syncthreads();                // all gathers done before rows are overwritten
#pragma unroll
        for (int a = 0; a < 16; ++a) {
            float x, y; upk2(vr[a], x, y);
            B0[(2 * a) * PITCH]     = x;
            B0[(2 * a + 1) * PITCH] = y;
        }
#pragma unroll
        for (int a = 16; a < 32; ++a) {
            float x, y; upk2(vr[a], x, y);
            B1[(2 * a - 32) * PITCH] = x;
            B1[(2 * a - 31) * PITCH] = y;
        }
        __syncthreads();

        // ===== pass 2: linear in-place, RY qubits 5..0 =====
        // fold q5 (component, scalar on fresh loads) and q4 (packed) into the load
        u64 vp[32];
        {
            float t5 = tcv[5], t4 = tcv[4];
            u64 tn4 = pk2(-t4, -t4), tp4 = pk2(t4, t4);
#pragma unroll
            for (int g = 0; g < 16; ++g) {
                float4 f = *reinterpret_cast<const float4*>(pld + 4 * g);
                float a0 = fmaf(-t5, f.y, f.x);
                float a1 = fmaf( t5, f.x, f.y);
                float b0 = fmaf(-t5, f.w, f.z);
                float b1 = fmaf( t5, f.z, f.w);
                u64 lo = pk2(a0, a1), hi = pk2(b0, b1);
                vp[2 * g]     = ffma2(tn4, hi, lo);   // q4 across i7
                vp[2 * g + 1] = ffma2(tp4, lo, hi);
            }
        }
        vstage<1>(vp, tcv[3]);
        vstage<2>(vp, tcv[2]);
        vstage<3>(vp, tcv[1]);
        vstage<4>(vp, tcv[0]);

        if (L < 19) {
#pragma unroll
            for (int g = 0; g < 16; ++g) {
                float x0, y0, x1, y1;
                upk2(vp[2 * g], x0, y0);
                upk2(vp[2 * g + 1], x1, y1);
                *reinterpret_cast<float4*>(pld + 4 * g) = make_float4(x0, y0, x1, y1);
            }
            __syncthreads();
        } else {
            // ===== expvals from registers =====
            // component = i6 (q5); pair bits b0..b4 = i7..i11 (q4..q0); u = i0..i5 (q11..q6)
            float S = 0.f, Ty = 0.f, T0 = 0.f, T1 = 0.f, T2 = 0.f, T3 = 0.f, T4 = 0.f;
#pragma unroll
            for (int a = 0; a < 32; ++a) {
                float x, y; upk2(vp[a], x, y);
                float px = x * x, py = y * y, ps = px + py;
                S += ps; Ty += py;
                if (a & 1)  T0 += ps;
                if (a & 2)  T1 += ps;
                if (a & 4)  T2 += ps;
                if (a & 8)  T3 += ps;
                if (a & 16) T4 += ps;
            }
            float val[12];
            val[0] = S - 2.f * T4;
            val[1] = S - 2.f * T3;
            val[2] = S - 2.f * T2;
            val[3] = S - 2.f * T1;
            val[4] = S - 2.f * T0;
            val[5] = S - 2.f * Ty;
#pragma unroll
            for (int q = 6; q < 12; ++q)
                val[q] = ((u >> (11 - q)) & 1) ? -S : S;
#pragma unroll
            for (int q = 0; q < 12; ++q) {
#pragma unroll
                for (int o = 16; o; o >>= 1)
                    val[q] += __shfl_xor_sync(~0u, val[q], o);
            }
            if (lane == 0) {
#pragma unroll
                for (int q = 0; q < 12; ++q) rsum[u >> 5][q] = val[q];
            }
        }
    }

    __syncthreads();
    if (u < 12) {
        out[(size_t)b * 12 + u] = (rsum[0][u] + rsum[1][u]) * oscale_s;
    }
}

extern "C" void kernel_launch(void* const* d_in, const int* in_sizes, int n_in,
                              void* d_out, int out_size) {
    const float* feats = (const float*)d_in[0];
    const float* qp    = (const float*)d_in[1];
    float* out         = (float*)d_out;
    qsim_kernel<<<4096, NT>>>(feats, qp, out);
}

// round 14
// speedup vs baseline: 1.0384x; 1.0002x over previous
#include <cuda_runtime.h>

#define NT 64
typedef unsigned long long u64;

__device__ __forceinline__ u64 pk2(float x, float y) {
    u64 r; asm("mov.b64 %0,{%1,%2};" : "=l"(r) : "f"(x), "f"(y)); return r;
}
__device__ __forceinline__ void upk2(u64 v, float& x, float& y) {
    asm("mov.b64 {%0,%1},%2;" : "=f"(x), "=f"(y) : "l"(v));
}
__device__ __forceinline__ u64 ffma2(u64 a, u64 b, u64 c) {
    u64 d; asm("fma.rn.f32x2 %0,%1,%2,%3;" : "=l"(d) : "l"(a), "l"(b), "l"(c)); return d;
}

// packed butterfly over pair-index bit B
template <int B>
__device__ __forceinline__ void vstage(u64* v, float t) {
    u64 tp = pk2(t, t), tn = pk2(-t, -t);
#pragma unroll
    for (int a = 0; a < 32; ++a)
        if (!(a & (1 << B))) {
            u64 A = v[a], Bv = v[a | (1 << B)];
            v[a]            = ffma2(tn, Bv, A);
            v[a | (1 << B)] = ffma2(tp, A, Bv);
        }
}

// register-pair index for pass-1 load row-pair q: a = (f0^{-1}(2q)) >> 1
__device__ __forceinline__ constexpr int AQ(int q) {
    int q0 = q & 1, q1 = (q >> 1) & 1, q2 = (q >> 2) & 1, q3 = (q >> 3) & 1, q4 = (q >> 4) & 1;
    return (q0 ^ q1 ^ q2) | ((q1 ^ q2) << 1) | ((q2 ^ q3 ^ q4) << 2)
         | ((q3 ^ q4) << 3) | (q4 << 4);
}

#define PITCH 68

__global__ void __launch_bounds__(NT, 11)
qsim_kernel(const float* __restrict__ feats,
            const float* __restrict__ qp,
            float* __restrict__ out)
{
    // layout T: element (i_lo, i_hi) at i_lo*PITCH + i_hi  (pad 68 -> bank rot by 4/row)
    __shared__ float buf[64 * PITCH];
    __shared__ float tt[240];
    __shared__ float wred[2], gred[2];
    __shared__ float oscale_s;
    __shared__ float rsum[2][12];

    const int u    = threadIdx.x;   // 0..63
    const int lane = u & 31;
    const int b    = blockIdx.x;

    // ---- phase stagger: co-resident CTAs are b0 + 148k; 148 = 5 (mod 11), so the
    // 11 CTAs on one SM get 11 distinct offsets -> breaks crossbar lock-step.
    __nanosleep(150u * (unsigned)(b % 11));

    // tan table + global cos product (cos factors -> output scale G^2)
    float gpart = 1.0f;
    for (int i = u; i < 240; i += NT) {
        float s, c; sincosf(0.5f * qp[12 + i], &s, &c);
        tt[i] = s / c; gpart *= c;
    }
#pragma unroll
    for (int o = 16; o; o >>= 1) gpart *= __shfl_xor_sync(~0u, gpart, o);
    if (lane == 0) gred[u >> 5] = gpart;

    // embedding: raw state into T layout (elem s at (s&63)*PITCH + (s>>6))
    const float2* f2 = reinterpret_cast<const float2*>(feats + (size_t)b * 2048);
    const float PIO2 = 1.5707963267948966f;
    float acc = 8.0f;
#pragma unroll
    for (int v = 0; v < 16; ++v) {
        int p = v * 64 + u;
        float2 x = f2[p];
        float y0 = tanhf(x.x) * PIO2;
        float y1 = tanhf(x.y) * PIO2;
        acc += y0 * y0 + y1 * y1;
        int s = 2 * p;
        buf[(s & 63) * PITCH + (s >> 6)]       = y0;
        buf[((s + 1) & 63) * PITCH + (s >> 6)] = y1;
    }
#pragma unroll
    for (int v = 16; v < 32; ++v) {
        int s = 2 * (v * 64 + u);
        buf[(s & 63) * PITCH + (s >> 6)]       = 0.5f;
        buf[((s + 1) & 63) * PITCH + (s >> 6)] = 0.5f;
    }
#pragma unroll
    for (int o = 16; o; o >>= 1) acc += __shfl_xor_sync(~0u, acc, o);
    if (lane == 0) wred[u >> 5] = acc;
    __syncthreads();
    if (u == 0) {
        float G = gred[0] * gred[1];
        oscale_s = (G * G) / (wred[0] + wred[1]);
    }

    // per-thread constants
    // i_hi = H(u) = Mhi^{-1}(u)
    int u0 = u & 1, u1 = (u >> 1) & 1, u2b = (u >> 2) & 1;
    int u3 = (u >> 3) & 1, u4 = (u >> 4) & 1, u5 = (u >> 5) & 1;
    int Hh = (u0 ^ u1) | ((u1 ^ u2b ^ u3) << 1) | ((u2b ^ u3) << 2)
           | ((u3 ^ u4 ^ u5) << 3) | ((u4 ^ u5) << 4) | (u5 << 5);
    int e = u0 ^ u1;                         // i6 of this thread's dst block
    const float* pL = buf + u;               // pass-1 load base (col u, + m*PITCH imm)
    float* B0 = buf + Hh + (e ? 32 * PITCH : 0);   // pass-1 store, rows 0..31
    float* B1 = buf + Hh + (e ? 0 : 32 * PITCH);   // pass-1 store, rows 32..63
    float* pld = buf + u * PITCH;            // pass-2 base (in-place)
    float esgn = e ? -1.0f : 1.0f;

#pragma unroll 1
    for (int L = 0; L < 20; ++L) {
        const float* tc = &tt[L * 12];

        // ===== pass 1: entangling gather (addressing-free) + RY qubits 11..6 =====
        u64 vr[32];
        {
            float t11 = tc[11];
            u64 tm = pk2(-t11, t11);
#pragma unroll
            for (int q = 0; q < 32; ++q) {
                float A = pL[(2 * q) * PITCH];
                float Bv = pL[(2 * q + 1) * PITCH];
                u64 ab = pk2(A, Bv), ba = pk2(Bv, A);
                // role: even row holds comp0 iff (q&1)==0 (compile-time select)
                vr[AQ(q)] = (q & 1) ? ffma2(tm, ab, ba) : ffma2(tm, ba, ab);
            }
        }
        vstage<0>(vr, tc[10]);
        vstage<1>(vr, tc[9]);
        vstage<2>(vr, tc[8]);
        vstage<3>(vr, tc[7]);
        vstage<4>(vr, esgn * tc[6]);   // e-swapped pairing on bit5 => R(-t)
        __syncthreads();               // all gathers done before rows are overwritten
#pragma unroll
        for (int a = 0; a < 16; ++a) {
            float x, y; upk2(vr[a], x, y);
            B0[(2 * a) * PITCH]     = x;
            B0[(2 * a + 1) * PITCH] = y;
        }
#pragma unroll
        for (int a = 16; a < 32; ++a) {
            float x, y; upk2(vr[a], x, y);
            B1[(2 * a - 32) * PITCH] = x;
            B1[(2 * a - 31) * PITCH] = y;
        }
        __syncthreads();

        // ===== pass 2: linear in-place, RY qubits 5..0 =====
        // fold q5 (component, scalar on fresh loads) and q4 (packed) into the load
        u64 vp[32];
        {
            float t5 = tc[5], t4 = tc[4];
            u64 tn4 = pk2(-t4, -t4), tp4 = pk2(t4, t4);
#pragma unroll
            for (int g = 0; g < 16; ++g) {
                float4 f = *reinterpret_cast<const float4*>(pld + 4 * g);
                float a0 = fmaf(-t5, f.y, f.x);
                float a1 = fmaf( t5, f.x, f.y);
                float b0 = fmaf(-t5, f.w, f.z);
                float b1 = fmaf( t5, f.z, f.w);
                u64 lo = pk2(a0, a1), hi = pk2(b0, b1);
                vp[2 * g]     = ffma2(tn4, hi, lo);   // q4 across i7
                vp[2 * g + 1] = ffma2(tp4, lo, hi);
            }
        }
        vstage<1>(vp, tc[3]);
        vstage<2>(vp, tc[2]);
        vstage<3>(vp, tc[1]);
        vstage<4>(vp, tc[0]);

        if (L < 19) {
#pragma unroll
            for (int g = 0; g < 16; ++g) {
                float x0, y0, x1, y1;
                upk2(vp[2 * g], x0, y0);
                upk2(vp[2 * g + 1], x1, y1);
                *reinterpret_cast<float4*>(pld + 4 * g) = make_float4(x0, y0, x1, y1);
            }
            __syncthreads();
        } else {
            // ===== expvals from registers =====
            // component = i6 (q5); pair bits b0..b4 = i7..i11 (q4..q0); u = i0..i5 (q11..q6)
            float S = 0.f, Ty = 0.f, T0 = 0.f, T1 = 0.f, T2 = 0.f, T3 = 0.f, T4 = 0.f;
#pragma unroll
            for (int a = 0; a < 32; ++a) {
                float x, y; upk2(vp[a], x, y);
                float px = x * x, py = y * y, ps = px + py;
                S += ps; Ty += py;
                if (a & 1)  T0 += ps;
                if (a & 2)  T1 += ps;
                if (a & 4)  T2 += ps;
                if (a & 8)  T3 += ps;
                if (a & 16) T4 += ps;
            }
            float val[12];
            val[0] = S - 2.f * T4;
            val[1] = S - 2.f * T3;
            val[2] = S - 2.f * T2;
            val[3] = S - 2.f * T1;
            val[4] = S - 2.f * T0;
            val[5] = S - 2.f * Ty;
#pragma unroll
            for (int q = 6; q < 12; ++q)
                val[q] = ((u >> (11 - q)) & 1) ? -S : S;
#pragma unroll
            for (int q = 0; q < 12; ++q) {
#pragma unroll
                for (int o = 16; o; o >>= 1)
                    val[q] += __shfl_xor_sync(~0u, val[q], o);
            }
            if (lane == 0) {
#pragma unroll
                for (int q = 0; q < 12; ++q) rsum[u >> 5][q] = val[q];
            }
        }
    }

    __syncthreads();
    if (u < 12) {
        out[(size_t)b * 12 + u] = (rsum[0][u] + rsum[1][u]) * oscale_s;
    }
}

extern "C" void kernel_launch(void* const* d_in, const int* in_sizes, int n_in,
                              void* d_out, int out_size) {
    const float* feats = (const float*)d_in[0];
    const float* qp    = (const float*)d_in[1];
    float* out         = (float*)d_out;
    qsim_kernel<<<4096, NT>>>(feats, qp, out);
}